// round 1
// baseline (speedup 1.0000x reference)
#include <cuda_runtime.h>
#include <cstdint>

#define F      1024
#define ROWS   256
#define MAXB   256
#define DOMS   8
#define EPSV   1e-5f

// ---------------- scratch (static device globals; no allocation) ----------------
__device__ int    g_is64;
__device__ int    g_pcnt[MAXB * DOMS];
__device__ float  g_psum[(size_t)MAXB * DOMS * F];   // 8 MB
__device__ float  g_psq [(size_t)MAXB * DOMS * F];   // 8 MB
__device__ float2 g_tab [DOMS * F];                  // (scale, bias) per (d,f)

// ---------------- y dtype detection (int64 vs int32) ----------------
// If y is little-endian int64 with values in [0,8), every odd 32-bit word is 0.
// If y is int32, odd words are random values in [0,8) -> some nonzero w.p. ~1.
__global__ void detect_k(const unsigned int* __restrict__ yw) {
    int t = 0;
    for (int i = threadIdx.x; i < 2048; i += blockDim.x)
        if (yw[2 * i + 1] != 0u) t = 1;
    int any = __syncthreads_or(t);
    if (threadIdx.x == 0) g_is64 = any ? 0 : 1;
}

// ---------------- per-block counting sort of rows by domain ----------------
__device__ __forceinline__ void sort_rows(const void* yv, int b, int nrows,
                                          int* ys, unsigned short* perm,
                                          unsigned char* dsort, int* cnt, int* off) {
    int tid = threadIdx.x;
    if (tid < DOMS) cnt[tid] = 0;
    __syncthreads();
    if (tid < nrows) {
        long long gi = (long long)b * ROWS + tid;
        int d;
        if (g_is64) d = (int)((const long long*)yv)[gi];
        else        d = ((const int*)yv)[gi];
        ys[tid] = d;
        atomicAdd(&cnt[d], 1);
    }
    __syncthreads();
    if (tid == 0) {
        int run = 0;
        #pragma unroll
        for (int d = 0; d < DOMS; d++) { off[d] = run; run += cnt[d]; }
    }
    __syncthreads();
    if (tid < nrows) {
        int d = ys[tid];
        int pos = atomicAdd(&off[d], 1);
        perm[pos]  = (unsigned short)tid;
        dsort[pos] = (unsigned char)d;
    }
    __syncthreads();
}

// ---------------- pass 1: per-block per-(d,f) sum & sumsq partials ----------------
__global__ void __launch_bounds__(1024) pass1_k(const float* __restrict__ x,
                                                const void* __restrict__ yv, int n) {
    __shared__ int ys[ROWS];
    __shared__ unsigned short perm[ROWS];
    __shared__ unsigned char dsort[ROWS];
    __shared__ int cnt[DOMS], off[DOMS];

    int b = blockIdx.x;
    int nrows = min(ROWS, n - b * ROWS);
    if (nrows <= 0) return;
    sort_rows(yv, b, nrows, ys, perm, dsort, cnt, off);

    int f = threadIdx.x;
    const float* xb = x + (size_t)b * ROWS * F + f;
    float* psum = g_psum + (size_t)b * DOMS * F;
    float* psq  = g_psq  + (size_t)b * DOMS * F;

    float s = 0.f, q = 0.f;
    int cur = dsort[0];
    #pragma unroll 4
    for (int r = 0; r < nrows; r++) {
        int row = perm[r];
        int d   = dsort[r];
        float v = xb[(size_t)row * F];
        if (d != cur) {                    // warp-uniform branch (sorted order)
            psum[cur * F + f] = s;
            psq [cur * F + f] = q;
            s = 0.f; q = 0.f; cur = d;
        }
        s += v;
        q = fmaf(v, v, q);
    }
    psum[cur * F + f] = s;
    psq [cur * F + f] = q;

    // zero partials for domains absent from this block
    #pragma unroll
    for (int d = 0; d < DOMS; d++)
        if (cnt[d] == 0) { psum[d * F + f] = 0.f; psq[d * F + f] = 0.f; }

    if (f < DOMS) g_pcnt[b * DOMS + f] = cnt[f];
}

// ---------------- reduce: partials -> (scale, bias) table ----------------
__global__ void __launch_bounds__(1024) reduce_k(const float* __restrict__ gamma,
                                                 const float* __restrict__ beta,
                                                 int nblocks) {
    __shared__ int scnt[DOMS];
    int j = blockIdx.x * 1024 + threadIdx.x;   // 0..8191 -> (d,f)
    if (threadIdx.x < DOMS) {
        int c = 0;
        for (int b = 0; b < nblocks; b++) c += g_pcnt[b * DOMS + threadIdx.x];
        scnt[threadIdx.x] = c;
    }
    __syncthreads();

    int d = j >> 10, f = j & (F - 1);
    float s = 0.f, q = 0.f;
    #pragma unroll 8
    for (int b = 0; b < nblocks; b++) {
        s += g_psum[(size_t)b * DOMS * F + j];
        q += g_psq [(size_t)b * DOMS * F + j];
    }
    float c = (float)scnt[d];
    float sc, bi;
    if (c > 1.f) {
        float inv  = 1.f / c;
        float mean = s * inv;
        float var  = fmaxf(q * inv - mean * mean, 0.f);
        sc = gamma[f] * rsqrtf(var + EPSV);
        bi = fmaf(-mean, sc, beta[f]);
    } else if (c == 1.f) {
        sc = 1.f; bi = 0.f;                    // count==1 -> raw x
    } else {
        sc = 0.f; bi = 0.f;                    // count==0 -> 0
    }
    g_tab[j] = make_float2(sc, bi);
}

// ---------------- pass 2: normalize + affine ----------------
__global__ void __launch_bounds__(1024) pass2_k(const float* __restrict__ x,
                                                const void* __restrict__ yv,
                                                float* __restrict__ out, int n) {
    __shared__ int ys[ROWS];
    __shared__ unsigned short perm[ROWS];
    __shared__ unsigned char dsort[ROWS];
    __shared__ int cnt[DOMS], off[DOMS];

    int b = blockIdx.x;
    int nrows = min(ROWS, n - b * ROWS);
    if (nrows <= 0) return;
    sort_rows(yv, b, nrows, ys, perm, dsort, cnt, off);

    int f = threadIdx.x;
    const float* xb = x   + (size_t)b * ROWS * F + f;
    float*       ob = out + (size_t)b * ROWS * F + f;

    int cur = dsort[0];
    float2 sb = g_tab[cur * F + f];
    #pragma unroll 4
    for (int r = 0; r < nrows; r++) {
        int row = perm[r];
        int d   = dsort[r];
        if (d != cur) { cur = d; sb = g_tab[cur * F + f]; }
        float v = xb[(size_t)row * F];
        ob[(size_t)row * F] = fmaf(v, sb.x, sb.y);
    }
}

// ---------------- launch ----------------
extern "C" void kernel_launch(void* const* d_in, const int* in_sizes, int n_in,
                              void* d_out, int out_size) {
    const float* x     = (const float*)d_in[0];
    const void*  y     = d_in[1];
    const float* gamma = (const float*)d_in[2];
    const float* beta  = (const float*)d_in[3];
    float*       out   = (float*)d_out;

    int n  = in_sizes[1];                 // batch (element count of y)
    int nb = (n + ROWS - 1) / ROWS;       // 256 for n=65536

    detect_k<<<1, 256>>>((const unsigned int*)y);
    pass1_k <<<nb, 1024>>>(x, y, n);
    reduce_k<<<DOMS * F / 1024, 1024>>>(gamma, beta, nb);
    pass2_k <<<nb, 1024>>>(x, y, out, n);
}

// round 2
// speedup vs baseline: 1.3678x; 1.3678x over previous
#include <cuda_runtime.h>
#include <cstdint>

#define F       1024
#define F4      (F / 4)
#define SLAB    128
#define MAXSLB  1024
#define DOMS    8
#define NGRP    8
#define EPSV    1e-5f

// ---------------- scratch (static device globals; no allocation) ----------------
__device__ int    g_is64;
__device__ int    g_pcnt[MAXSLB * DOMS];
__device__ float  g_psum[(size_t)MAXSLB * DOMS * F];   // 32 MB
__device__ float  g_psq [(size_t)MAXSLB * DOMS * F];   // 32 MB
__device__ float  g_rsum[NGRP * DOMS * F];
__device__ float  g_rsq [NGRP * DOMS * F];
__device__ int    g_rcnt[NGRP * DOMS];
__device__ float  g_scale[DOMS * F];
__device__ float  g_bias [DOMS * F];

// ---------------- y dtype detection (int64 vs int32) ----------------
__global__ void detect_k(const unsigned int* __restrict__ yw, int n) {
    int lim = min(2048, (n - 1) / 2);
    int t = 0;
    for (int i = threadIdx.x; i < lim; i += blockDim.x)
        if (yw[2 * i + 1] != 0u) t = 1;
    int any = __syncthreads_or(t);
    if (threadIdx.x == 0) g_is64 = any ? 0 : 1;
}

// ---------------- pass 1: sorted-run register accumulation, float4 lanes ----------------
__global__ void __launch_bounds__(256) pass1_k(const float4* __restrict__ x,
                                               const void* __restrict__ yv, int n) {
    __shared__ int ysm[SLAB];
    __shared__ unsigned short perm[SLAB];
    __shared__ unsigned char dsort[SLAB];
    __shared__ int cnt[DOMS], off[DOMS];

    int slab = blockIdx.x;
    int base = slab * SLAB;
    int nrows = min(SLAB, n - base);
    if (nrows <= 0) return;
    int tid = threadIdx.x;

    // counting sort of this slab's rows by domain
    if (tid < DOMS) cnt[tid] = 0;
    __syncthreads();
    if (tid < nrows) {
        int d = g_is64 ? (int)((const long long*)yv)[base + tid]
                       : ((const int*)yv)[base + tid];
        ysm[tid] = d;
        atomicAdd(&cnt[d], 1);
    }
    __syncthreads();
    if (tid == 0) {
        int run = 0;
        #pragma unroll
        for (int d = 0; d < DOMS; d++) { off[d] = run; run += cnt[d]; }
    }
    __syncthreads();
    if (tid < nrows) {
        int d = ysm[tid];
        int p = atomicAdd(&off[d], 1);
        perm[p]  = (unsigned short)tid;
        dsort[p] = (unsigned char)d;
    }
    __syncthreads();

    const float4* xb = x + (size_t)base * F4 + tid;
    float4* psum = (float4*)(g_psum + (size_t)slab * DOMS * F);
    float4* psq  = (float4*)(g_psq  + (size_t)slab * DOMS * F);

    float4 s = make_float4(0.f, 0.f, 0.f, 0.f);
    float4 q = make_float4(0.f, 0.f, 0.f, 0.f);
    int cur = dsort[0];

    int r = 0;
    for (; r + 8 <= nrows; r += 8) {
        float4 v[8]; int dd[8];
        #pragma unroll
        for (int i = 0; i < 8; i++) {
            int row = perm[r + i];
            dd[i] = dsort[r + i];
            v[i] = __ldcs(xb + (size_t)row * F4);
        }
        #pragma unroll
        for (int i = 0; i < 8; i++) {
            if (dd[i] != cur) {                    // warp-uniform (sorted)
                psum[cur * F4 + tid] = s;
                psq [cur * F4 + tid] = q;
                s = make_float4(0.f, 0.f, 0.f, 0.f);
                q = make_float4(0.f, 0.f, 0.f, 0.f);
                cur = dd[i];
            }
            s.x += v[i].x; s.y += v[i].y; s.z += v[i].z; s.w += v[i].w;
            q.x = fmaf(v[i].x, v[i].x, q.x);
            q.y = fmaf(v[i].y, v[i].y, q.y);
            q.z = fmaf(v[i].z, v[i].z, q.z);
            q.w = fmaf(v[i].w, v[i].w, q.w);
        }
    }
    for (; r < nrows; r++) {                       // tail
        int row = perm[r];
        int d = dsort[r];
        float4 v = __ldcs(xb + (size_t)row * F4);
        if (d != cur) {
            psum[cur * F4 + tid] = s;
            psq [cur * F4 + tid] = q;
            s = make_float4(0.f, 0.f, 0.f, 0.f);
            q = make_float4(0.f, 0.f, 0.f, 0.f);
            cur = d;
        }
        s.x += v.x; s.y += v.y; s.z += v.z; s.w += v.w;
        q.x = fmaf(v.x, v.x, q.x); q.y = fmaf(v.y, v.y, q.y);
        q.z = fmaf(v.z, v.z, q.z); q.w = fmaf(v.w, v.w, q.w);
    }
    psum[cur * F4 + tid] = s;
    psq [cur * F4 + tid] = q;

    float4 z = make_float4(0.f, 0.f, 0.f, 0.f);
    #pragma unroll
    for (int d = 0; d < DOMS; d++)
        if (cnt[d] == 0) { psum[d * F4 + tid] = z; psq[d * F4 + tid] = z; }

    if (tid < DOMS) g_pcnt[slab * DOMS + tid] = cnt[tid];
}

// ---------------- reduce stage A: 512 slabs -> NGRP group partials ----------------
__global__ void __launch_bounds__(256) reduceA_k(int nslabs) {
    int j = blockIdx.x * 256 + threadIdx.x;        // 0..8191, gridDim.x = 32
    int g = blockIdx.y;                            // 0..NGRP-1
    int chunk = (nslabs + NGRP - 1) / NGRP;
    int b0 = g * chunk;
    int b1 = min(nslabs, b0 + chunk);

    float s = 0.f, q = 0.f;
    #pragma unroll 4
    for (int b = b0; b < b1; b++) {
        s += g_psum[(size_t)b * (DOMS * F) + j];
        q += g_psq [(size_t)b * (DOMS * F) + j];
    }
    g_rsum[g * (DOMS * F) + j] = s;
    g_rsq [g * (DOMS * F) + j] = q;

    if (blockIdx.x == 0 && threadIdx.x < DOMS) {
        int c = 0;
        for (int b = b0; b < b1; b++) c += g_pcnt[b * DOMS + threadIdx.x];
        g_rcnt[g * DOMS + threadIdx.x] = c;
    }
}

// ---------------- reduce stage B: group partials -> (scale, bias) table ----------------
__global__ void __launch_bounds__(1024) reduceB_k(const float* __restrict__ gamma,
                                                  const float* __restrict__ beta) {
    __shared__ int scnt[DOMS];
    int j = blockIdx.x * 1024 + threadIdx.x;       // 0..8191, gridDim.x = 8

    if (threadIdx.x < DOMS) {
        int c = 0;
        #pragma unroll
        for (int g = 0; g < NGRP; g++) c += g_rcnt[g * DOMS + threadIdx.x];
        scnt[threadIdx.x] = c;
    }
    __syncthreads();

    float s = 0.f, q = 0.f;
    #pragma unroll
    for (int g = 0; g < NGRP; g++) {
        s += g_rsum[g * (DOMS * F) + j];
        q += g_rsq [g * (DOMS * F) + j];
    }
    int d = j >> 10, f = j & (F - 1);
    float c = (float)scnt[d];
    float sc, bi;
    if (c > 1.f) {
        float inv  = 1.f / c;
        float mean = s * inv;
        float var  = fmaxf(q * inv - mean * mean, 0.f);
        sc = gamma[f] * rsqrtf(var + EPSV);
        bi = fmaf(-mean, sc, beta[f]);
    } else if (c == 1.f) {
        sc = 1.f; bi = 0.f;
    } else {
        sc = 0.f; bi = 0.f;
    }
    g_scale[j] = sc;
    g_bias [j] = bi;
}

// ---------------- pass 2: pure streaming FMA (no sort, table in L1) ----------------
__global__ void __launch_bounds__(256) pass2_k(const float4* __restrict__ x,
                                               const void* __restrict__ yv,
                                               float4* __restrict__ out, int n) {
    size_t total  = (size_t)n * F4;
    size_t tid0   = (size_t)blockIdx.x * blockDim.x + threadIdx.x;
    size_t stride = (size_t)gridDim.x * blockDim.x;
    const float4* sc4 = (const float4*)g_scale;
    const float4* bi4 = (const float4*)g_bias;
    const int* yi = (const int*)yv;
    int sh = g_is64;                                // 1 -> low word of int64

    float4 v[8]; int dd[8];
    #pragma unroll
    for (int i = 0; i < 8; i++) {
        size_t j = tid0 + (size_t)i * stride;
        if (j < total) {
            size_t row = j >> 8;                    // j / F4
            dd[i] = yi[row << sh];
            v[i]  = __ldcs(x + j);
        }
    }
    #pragma unroll
    for (int i = 0; i < 8; i++) {
        size_t j = tid0 + (size_t)i * stride;
        if (j < total) {
            int f4 = (int)(j & (F4 - 1));
            float4 sc = sc4[dd[i] * F4 + f4];
            float4 bi = bi4[dd[i] * F4 + f4];
            float4 o;
            o.x = fmaf(v[i].x, sc.x, bi.x);
            o.y = fmaf(v[i].y, sc.y, bi.y);
            o.z = fmaf(v[i].z, sc.z, bi.z);
            o.w = fmaf(v[i].w, sc.w, bi.w);
            __stcs(out + j, o);
        }
    }
}

// ---------------- launch ----------------
extern "C" void kernel_launch(void* const* d_in, const int* in_sizes, int n_in,
                              void* d_out, int out_size) {
    const float4* x    = (const float4*)d_in[0];
    const void*   y    = d_in[1];
    const float*  gamma = (const float*)d_in[2];
    const float*  beta  = (const float*)d_in[3];
    float4*       out   = (float4*)d_out;

    int n       = in_sizes[1];                     // batch size (y element count)
    int nslabs  = (n + SLAB - 1) / SLAB;           // 512 for n=65536

    detect_k<<<1, 256>>>((const unsigned int*)y, n);
    pass1_k <<<nslabs, 256>>>(x, y, n);
    dim3 ga(DOMS * F / 256, NGRP);
    reduceA_k<<<ga, 256>>>(nslabs);
    reduceB_k<<<DOMS * F / 1024, 1024>>>(gamma, beta);

    size_t total   = (size_t)n * F4;
    int    blocks2 = (int)((total + 256 * 8 - 1) / (256 * 8));
    pass2_k<<<blocks2, 256>>>(x, y, out, n);
}

// round 3
// speedup vs baseline: 1.4003x; 1.0238x over previous
#include <cuda_runtime.h>
#include <cstdint>

#define F      1024
#define F4     256
#define DOMS   8
#define NBLK   296          // 2 CTAs/SM on 148 SMs (GB300 has 152 -> still co-resident)
#define TPB    256
#define RMAX   512          // max rows per block supported by smem arrays
#define EPSV   1e-5f

// ---------------- scratch (static device globals; no allocation) ----------------
__device__ int      g_is64;
__device__ unsigned g_ctr1, g_ctr2;
__device__ float    g_psum[(size_t)NBLK * DOMS * F];   // 9.7 MB
__device__ float    g_psq [(size_t)NBLK * DOMS * F];   // 9.7 MB
__device__ int      g_pcnt[NBLK * DOMS];
__device__ float    g_scale[DOMS * F];
__device__ float    g_bias [DOMS * F];

// ---------------- init: zero sync counters + detect y dtype ----------------
__global__ void init_k(const unsigned* __restrict__ yw, int n) {
    if (threadIdx.x == 0) { g_ctr1 = 0u; g_ctr2 = 0u; }
    int lim = min(2048, (n - 1) / 2);   // only touch words guaranteed in-bounds for int32
    int t = 0;
    for (int i = threadIdx.x; i < lim; i += blockDim.x)
        if (yw[2 * i + 1] != 0u) t = 1; // int64 y in [0,8) -> odd words all zero
    int any = __syncthreads_or(t);
    if (threadIdx.x == 0) g_is64 = any ? 0 : 1;
}

// ---------------- software grid barrier (all NBLK blocks co-resident) ----------------
__device__ __forceinline__ void gsync(unsigned* ctr) {
    __syncthreads();
    if (threadIdx.x == 0) {
        __threadfence();
        atomicAdd(ctr, 1u);
        volatile unsigned* vc = (volatile unsigned*)ctr;
        while (*vc < NBLK) __nanosleep(64);
        __threadfence();
    }
    __syncthreads();
}

// ---------------- fused persistent kernel ----------------
__global__ void __launch_bounds__(TPB, 2) fused_k(
    const float4* __restrict__ x, const void* __restrict__ yv,
    const float* __restrict__ gamma, const float* __restrict__ beta,
    float4* __restrict__ out, int n)
{
    __shared__ int            ysm[RMAX];
    __shared__ unsigned short perm[RMAX];
    __shared__ unsigned char  dsort[RMAX];
    __shared__ int            cnt[DOMS], off[DOMS], scnt[DOMS], cpart[64];
    __shared__ float          sred[9][28], qred[9][28];

    const int tid   = threadIdx.x;
    const int b     = blockIdx.x;
    const int rpb   = (n + NBLK - 1) / NBLK;        // 222 for n=65536
    const int base  = b * rpb;
    const int nrows = min(rpb, n - base);           // may be <=0 only if n < NBLK*rpb edge
    const int is64  = g_is64;

    // ================= Phase A: per-block sorted-run partial stats =================
    if (tid < DOMS) cnt[tid] = 0;
    __syncthreads();
    for (int i = tid; i < nrows; i += TPB) {
        int d = is64 ? (int)((const long long*)yv)[base + i]
                     : ((const int*)yv)[base + i];
        ysm[i] = d;
        atomicAdd(&cnt[d], 1);
    }
    __syncthreads();
    if (tid == 0) {
        int run = 0;
        #pragma unroll
        for (int d = 0; d < DOMS; d++) { off[d] = run; run += cnt[d]; }
    }
    __syncthreads();
    for (int i = tid; i < nrows; i += TPB) {
        int d = ysm[i];
        int p = atomicAdd(&off[d], 1);
        perm[p]  = (unsigned short)i;
        dsort[p] = (unsigned char)d;
    }
    __syncthreads();

    float4* psum = (float4*)(g_psum + (size_t)b * DOMS * F);
    float4* psq  = (float4*)(g_psq  + (size_t)b * DOMS * F);
    const float4* xb = x + (size_t)base * F4 + tid;

    if (nrows > 0) {
        float4 s = make_float4(0.f, 0.f, 0.f, 0.f);
        float4 q = make_float4(0.f, 0.f, 0.f, 0.f);
        int cur = dsort[0];
        int r = 0;
        for (; r + 8 <= nrows; r += 8) {
            float4 v[8]; int dd[8];
            #pragma unroll
            for (int i = 0; i < 8; i++) {
                dd[i] = dsort[r + i];
                v[i]  = xb[(size_t)perm[r + i] * F4];   // default load: keep in L2 for phase C
            }
            #pragma unroll
            for (int i = 0; i < 8; i++) {
                if (dd[i] != cur) {                      // warp-uniform (sorted)
                    psum[cur * F4 + tid] = s;
                    psq [cur * F4 + tid] = q;
                    s = make_float4(0.f, 0.f, 0.f, 0.f);
                    q = make_float4(0.f, 0.f, 0.f, 0.f);
                    cur = dd[i];
                }
                s.x += v[i].x; s.y += v[i].y; s.z += v[i].z; s.w += v[i].w;
                q.x = fmaf(v[i].x, v[i].x, q.x);
                q.y = fmaf(v[i].y, v[i].y, q.y);
                q.z = fmaf(v[i].z, v[i].z, q.z);
                q.w = fmaf(v[i].w, v[i].w, q.w);
            }
        }
        for (; r < nrows; r++) {
            int d = dsort[r];
            float4 v = xb[(size_t)perm[r] * F4];
            if (d != cur) {
                psum[cur * F4 + tid] = s;
                psq [cur * F4 + tid] = q;
                s = make_float4(0.f, 0.f, 0.f, 0.f);
                q = make_float4(0.f, 0.f, 0.f, 0.f);
                cur = d;
            }
            s.x += v.x; s.y += v.y; s.z += v.z; s.w += v.w;
            q.x = fmaf(v.x, v.x, q.x); q.y = fmaf(v.y, v.y, q.y);
            q.z = fmaf(v.z, v.z, q.z); q.w = fmaf(v.w, v.w, q.w);
        }
        psum[cur * F4 + tid] = s;
        psq [cur * F4 + tid] = q;
    }
    {
        float4 z = make_float4(0.f, 0.f, 0.f, 0.f);
        #pragma unroll
        for (int d = 0; d < DOMS; d++)
            if (cnt[d] == 0) { psum[d * F4 + tid] = z; psq[d * F4 + tid] = z; }
    }
    if (tid < DOMS) g_pcnt[b * DOMS + tid] = (nrows > 0) ? cnt[tid] : 0;

    gsync(&g_ctr1);

    // ================= Phase B: distributed reduce -> (scale, bias) table =================
    {
        // per-domain total counts: 64 threads (8 dom x 8 slab-groups), then fold
        if (tid < 64) {
            int d = tid & 7, g = tid >> 3;
            int s0 = g * 37, s1 = min(NBLK, s0 + 37);
            int c = 0;
            for (int s = s0; s < s1; s++) c += g_pcnt[s * DOMS + d];
            cpart[tid] = c;
        }
        __syncthreads();
        if (tid < DOMS) {
            int c = 0;
            #pragma unroll
            for (int g = 0; g < 8; g++) c += cpart[g * 8 + tid];
            scnt[tid] = c;
        }

        // positions: each block owns 28 consecutive (d,f) slots; 293 blocks cover 8192
        const int start = b * 28;
        const int p = tid % 28, c = tid / 28;       // c in 0..9 (c==9 idle)
        if (c < 9 && start + p < DOMS * F) {
            int j  = start + p;
            int s0 = c * 33, s1 = min(NBLK, s0 + 33);
            float s = 0.f, q = 0.f;
            for (int sl = s0; sl < s1; sl++) {
                s += g_psum[(size_t)sl * DOMS * F + j];
                q += g_psq [(size_t)sl * DOMS * F + j];
            }
            sred[c][p] = s; qred[c][p] = q;
        }
        __syncthreads();
        if (tid < 28 && start + tid < DOMS * F) {
            int jj = start + tid;
            float s = 0.f, q = 0.f;
            #pragma unroll
            for (int cc = 0; cc < 9; cc++) { s += sred[cc][tid]; q += qred[cc][tid]; }
            int d = jj >> 10, f = jj & (F - 1);
            float cf = (float)scnt[d];
            float sc, bi;
            if (cf > 1.f) {
                float inv  = 1.f / cf;
                float mean = s * inv;
                float var  = fmaxf(q * inv - mean * mean, 0.f);
                sc = gamma[f] * rsqrtf(var + EPSV);
                bi = fmaf(-mean, sc, beta[f]);
            } else if (cf == 1.f) { sc = 1.f; bi = 0.f; }   // count==1 -> raw x
            else                  { sc = 0.f; bi = 0.f; }   // count==0 -> 0
            g_scale[jj] = sc;
            g_bias [jj] = bi;
        }
    }

    gsync(&g_ctr2);

    // ================= Phase C: normalize own chunk, reverse of phase-A read order =================
    // LRU-perfect replay of this block's x lines still in L2; streaming stores.
    if (nrows > 0) {
        const float4* sc4 = (const float4*)g_scale;
        const float4* bi4 = (const float4*)g_bias;
        const float4* xc  = x   + (size_t)base * F4 + tid;
        float4*       oc  = out + (size_t)base * F4 + tid;

        for (int r = nrows - 1; r >= 0; r -= 8) {
            float4 v[8]; int row[8]; float4 sc[8], bi[8];
            #pragma unroll
            for (int i = 0; i < 8; i++) {
                int rr = r - i;
                if (rr >= 0) {
                    row[i] = perm[rr];
                    int d  = dsort[rr];
                    v[i]   = xc[(size_t)row[i] * F4];
                    sc[i]  = sc4[d * F4 + tid];
                    bi[i]  = bi4[d * F4 + tid];
                }
            }
            #pragma unroll
            for (int i = 0; i < 8; i++) {
                int rr = r - i;
                if (rr >= 0) {
                    float4 o;
                    o.x = fmaf(v[i].x, sc[i].x, bi[i].x);
                    o.y = fmaf(v[i].y, sc[i].y, bi[i].y);
                    o.z = fmaf(v[i].z, sc[i].z, bi[i].z);
                    o.w = fmaf(v[i].w, sc[i].w, bi[i].w);
                    __stcs(oc + (size_t)row[i] * F4, o);
                }
            }
        }
    }
}

// ---------------- launch ----------------
extern "C" void kernel_launch(void* const* d_in, const int* in_sizes, int n_in,
                              void* d_out, int out_size) {
    const float4* x     = (const float4*)d_in[0];
    const void*   y     = d_in[1];
    const float*  gamma = (const float*)d_in[2];
    const float*  beta  = (const float*)d_in[3];
    float4*       out   = (float4*)d_out;

    int n = in_sizes[1];   // batch (y element count)

    init_k <<<1, 256>>>((const unsigned*)y, n);
    fused_k<<<NBLK, TPB>>>(x, y, gamma, beta, out, n);
}